// round 13
// baseline (speedup 1.0000x reference)
#include <cuda_runtime.h>
#include <math.h>
#include <cstdint>

#define D 64
#define GMAX 256
#define N_MAX 100000
#define E_MAX 1200000
#define KC 8
#define BNEPS 1e-5f
#define NB_MAX 400

// ------------------- scratch (static device globals; no allocation) -------------------
__device__ __align__(16) float d_ya[(size_t)N_MAX * D];
__device__ __align__(16) float d_yb[(size_t)N_MAX * D];
__device__ __align__(16) float d_p [(size_t)N_MAX * D];
__device__ float d_degw[N_MAX];
__device__ int   d_cnt[N_MAX];
__device__ int   d_fill[N_MAX];
__device__ int   d_rowstart[N_MAX];
__device__ int   d_blksum[64];
__device__ __align__(16) int2 d_edge[E_MAX];   // (src, attr bits)
__device__ int   d_gcount[GMAX];
__device__ int   d_goff[GMAX + 1];
__device__ float d_bnpart_s[NB_MAX][D];
__device__ float d_bnpart_q[NB_MAX][D];
__device__ __align__(16) float d_scale[3][D];
__device__ __align__(16) float d_shift[3][D];
// folded layer-0 params
__device__ __align__(16) float d_M1[4 * D];
__device__ __align__(16) float d_M2[4 * D];
__device__ __align__(16) float d_M3[4 * D];
__device__ __align__(16) float d_u[D];
__device__ __align__(16) float d_v[D];

__device__ __forceinline__ float* nodebuf(int s) {
    return (s == 1) ? d_ya : d_yb;
}

// packed fp32x2 FMA (sm_100+)
__device__ __forceinline__ void fma2(unsigned long long& d,
                                     unsigned long long a,
                                     unsigned long long b) {
    asm("fma.rn.f32x2 %0, %1, %2, %0;" : "+l"(d) : "l"(a), "l"(b));
}
__device__ __forceinline__ unsigned long long dup2(float v) {
    unsigned long long d;
    int b = __float_as_int(v);
    asm("mov.b64 %0, {%1, %2};" : "=l"(d) : "r"(b), "r"(b));
    return d;
}

// ------------------- init + folded layer-0 param prep -------------------
__global__ void k_zero(const float* __restrict__ W_emb, const float* __restrict__ b_emb,
                       const float* __restrict__ W1, const float* __restrict__ b1,
                       const float* __restrict__ W2, const float* __restrict__ W3,
                       const float* __restrict__ b3, int n) {
    int i = blockIdx.x * blockDim.x + threadIdx.x;
    if (i < n) d_cnt[i] = 0;
    if (i < GMAX) d_gcount[i] = 0;
    if (blockIdx.x == 0) {
        int t = threadIdx.x;
        int j = t >> 6, c = t & 63;
        float a1 = 0.f, a2 = 0.f, a3 = 0.f;
        #pragma unroll 4
        for (int k = 0; k < 64; k++) {
            float we = W_emb[j * 64 + k];
            a1 = fmaf(we, W1[k * 64 + c], a1);
            a2 = fmaf(we, W2[k * 64 + c], a2);
            a3 = fmaf(we, W3[k * 64 + c], a3);
        }
        d_M1[j * 64 + c] = a1;
        d_M2[j * 64 + c] = a2;
        d_M3[j * 64 + c] = a3;
        if (t < 64) {
            float u = b1[t], v = b3[t];
            #pragma unroll 4
            for (int k = 0; k < 64; k++) {
                float be = b_emb[k];
                u = fmaf(be, W1[k * 64 + t] - W2[k * 64 + t], u);
                v = fmaf(be, W3[k * 64 + t], v);
            }
            d_u[t] = u;
            d_v[t] = v;
        }
    }
}

// ------------------- CSR build pass 1 + graph histogram -------------------
__global__ void k_epass1(const int* __restrict__ eid, const int* __restrict__ batch,
                         int E, int N) {
    int e = blockIdx.x * blockDim.x + threadIdx.x;
    if (e < E) atomicAdd(&d_cnt[eid[(size_t)E + e]], 1);
    if (e < N) atomicAdd(&d_gcount[batch[e]], 1);
}

__global__ void k_goff() {
    __shared__ int sh[GMAX];
    int t = threadIdx.x;
    int v = d_gcount[t];
    sh[t] = v; __syncthreads();
    for (int off = 1; off < GMAX; off <<= 1) {
        int add = (t >= off) ? sh[t - off] : 0;
        __syncthreads();
        sh[t] += add;
        __syncthreads();
    }
    d_goff[t + 1] = sh[t];
    if (t == 0) d_goff[0] = 0;
}

__global__ void k_scan1(int n) {
    __shared__ int sh[256];
    int t = threadIdx.x;
    int base = blockIdx.x * 4096 + t * 16;
    int v[16]; int tot = 0;
    #pragma unroll
    for (int i = 0; i < 16; i++) {
        int idx = base + i;
        v[i] = (idx < n) ? d_cnt[idx] : 0;
        tot += v[i];
    }
    sh[t] = tot; __syncthreads();
    for (int off = 1; off < 256; off <<= 1) {
        int add = (t >= off) ? sh[t - off] : 0;
        __syncthreads();
        sh[t] += add;
        __syncthreads();
    }
    int run = sh[t] - tot;
    #pragma unroll
    for (int i = 0; i < 16; i++) {
        int idx = base + i;
        if (idx < n) d_rowstart[idx] = run;
        run += v[i];
    }
    if (t == 255) d_blksum[blockIdx.x] = sh[255];
}

__global__ void k_scan2(int nb) {
    __shared__ int sh[256];
    int t = threadIdx.x;
    int v = (t < nb) ? d_blksum[t] : 0;
    sh[t] = v; __syncthreads();
    for (int off = 1; off < 256; off <<= 1) {
        int add = (t >= off) ? sh[t - off] : 0;
        __syncthreads();
        sh[t] += add;
        __syncthreads();
    }
    if (t < nb) d_blksum[t] = sh[t] - v;
}

__global__ void k_scan3(int n) {
    int i = blockIdx.x * blockDim.x + threadIdx.x;
    if (i < n) {
        int rs = d_rowstart[i] + d_blksum[i >> 12];
        d_rowstart[i] = rs;
        d_fill[i] = rs;
    }
}

__global__ void k_epass2(const int* __restrict__ eid, const float* __restrict__ attr, int E) {
    int e = blockIdx.x * blockDim.x + threadIdx.x;
    if (e >= E) return;
    int s  = eid[e];
    int dd = eid[(size_t)E + e];
    int pos = atomicAdd(&d_fill[dd], 1);
    d_edge[pos] = make_int2(s, __float_as_int(attr[e]));
}

// ---------- folded layer 0 (fused x-gather + combine) + BN stats; writes degw ----------
__global__ void __launch_bounds__(256) k_layer0(const float* __restrict__ x,
                                                const float* __restrict__ gamma,
                                                const float* __restrict__ beta, int n) {
    __shared__ __align__(16) float g_s[256][5];     // g[4] + degw per node
    __shared__ __align__(16) float bns[8][D + 1];
    __shared__ __align__(16) float bnq[8][D + 1];
    int t = threadIdx.x;
    int node0b = blockIdx.x * 256;
    float* __restrict__ y = d_ya;

    // phase 1: thread-per-node gather of x rows + degw (CSR row sum)
    {
        int node = node0b + t;
        float g0 = 0.f, g1 = 0.f, g2 = 0.f, g3 = 0.f, sw = 0.f;
        if (node < n) {
            int rs = d_rowstart[node];
            int re = rs + d_cnt[node];
            int j = rs;
            for (; j + 2 <= re; j += 2) {
                int2 e0 = d_edge[j];
                int2 e1 = d_edge[j + 1];
                float4 x0 = *(const float4*)(x + (size_t)e0.x * 4);
                float4 x1 = *(const float4*)(x + (size_t)e1.x * 4);
                float w0 = __int_as_float(e0.y), w1 = __int_as_float(e1.y);
                g0 = fmaf(w0, x0.x, g0); g1 = fmaf(w0, x0.y, g1);
                g2 = fmaf(w0, x0.z, g2); g3 = fmaf(w0, x0.w, g3);
                g0 = fmaf(w1, x1.x, g0); g1 = fmaf(w1, x1.y, g1);
                g2 = fmaf(w1, x1.z, g2); g3 = fmaf(w1, x1.w, g3);
                sw += w0 + w1;
            }
            if (j < re) {
                int2 e0 = d_edge[j];
                float4 x0 = *(const float4*)(x + (size_t)e0.x * 4);
                float w0 = __int_as_float(e0.y);
                g0 = fmaf(w0, x0.x, g0); g1 = fmaf(w0, x0.y, g1);
                g2 = fmaf(w0, x0.z, g2); g3 = fmaf(w0, x0.w, g3);
                sw += w0;
            }
            d_degw[node] = sw;
        }
        g_s[t][0] = g0; g_s[t][1] = g1; g_s[t][2] = g2; g_s[t][3] = g3; g_s[t][4] = sw;
    }
    __syncthreads();

    // phase 2: combine (lane = channel pair; warp covers 32 nodes)
    int cp = t & 31;
    int c0 = cp * 2;
    int wrp = t >> 5;
    int node0 = node0b + wrp * 32;

    float2 m1[4], m2[4], m3[4];
    #pragma unroll
    for (int k = 0; k < 4; k++) {
        m1[k] = *(const float2*)(d_M1 + k * 64 + c0);
        m2[k] = *(const float2*)(d_M2 + k * 64 + c0);
        m3[k] = *(const float2*)(d_M3 + k * 64 + c0);
    }
    float2 uv = *(const float2*)(d_u + c0);
    float2 vv = *(const float2*)(d_v + c0);

    float s0 = 0.f, s1 = 0.f, q0 = 0.f, q1 = 0.f;
    #pragma unroll 2
    for (int i = 0; i < 32; i++) {
        int node = node0 + i;
        if (node < n) {
            int lr = wrp * 32 + i;
            float gx = g_s[lr][0], gy = g_s[lr][1], gz = g_s[lr][2], gw = g_s[lr][3];
            float dwn = g_s[lr][4];
            float4 xr = *(const float4*)(x + (size_t)node * 4);
            float o0 = fmaf(dwn, uv.x, vv.x);
            float o1 = fmaf(dwn, uv.y, vv.y);
            o0 = fmaf(gx, m1[0].x, o0); o1 = fmaf(gx, m1[0].y, o1);
            o0 = fmaf(gy, m1[1].x, o0); o1 = fmaf(gy, m1[1].y, o1);
            o0 = fmaf(gz, m1[2].x, o0); o1 = fmaf(gz, m1[2].y, o1);
            o0 = fmaf(gw, m1[3].x, o0); o1 = fmaf(gw, m1[3].y, o1);
            float w20 = xr.x * m2[0].x, w21 = xr.x * m2[0].y;
            w20 = fmaf(xr.y, m2[1].x, w20); w21 = fmaf(xr.y, m2[1].y, w21);
            w20 = fmaf(xr.z, m2[2].x, w20); w21 = fmaf(xr.z, m2[2].y, w21);
            w20 = fmaf(xr.w, m2[3].x, w20); w21 = fmaf(xr.w, m2[3].y, w21);
            o0 = fmaf(-dwn, w20, o0);
            o1 = fmaf(-dwn, w21, o1);
            o0 = fmaf(xr.x, m3[0].x, o0); o1 = fmaf(xr.x, m3[0].y, o1);
            o0 = fmaf(xr.y, m3[1].x, o0); o1 = fmaf(xr.y, m3[1].y, o1);
            o0 = fmaf(xr.z, m3[2].x, o0); o1 = fmaf(xr.z, m3[2].y, o1);
            o0 = fmaf(xr.w, m3[3].x, o0); o1 = fmaf(xr.w, m3[3].y, o1);
            *(float2*)(y + (size_t)node * D + c0) = make_float2(o0, o1);
            s0 += o0; s1 += o1;
            q0 = fmaf(o0, o0, q0);
            q1 = fmaf(o1, o1, q1);
        }
    }
    bns[wrp][c0] = s0; bns[wrp][c0 + 1] = s1;
    bnq[wrp][c0] = q0; bnq[wrp][c0 + 1] = q1;
    __syncthreads();
    if (t < D) {
        float s = 0.f, q = 0.f;
        #pragma unroll
        for (int r = 0; r < 8; r++) { s += bns[r][t]; q += bnq[r][t]; }
        d_bnpart_s[blockIdx.x][t] = s;
        d_bnpart_q[blockIdx.x][t] = q;
    }
}

// ------------------- edge aggregation: p[i] = sum attr_e * hin[src_e] -------------------
// block = 256 CONSECUTIVE nodes (1-2 graphs); warp serially covers 32 nodes, lane =
// channel pair. Source rows stay within the block's graph(s) -> L1-resident reuse.
__global__ void __launch_bounds__(256) k_edge_agg(int insel, int slayer, int n) {
    const float* __restrict__ in = nodebuf(insel);
    int t = threadIdx.x;
    int lane = t & 31;
    int wrp = t >> 5;
    int c0 = lane * 2;
    float sc0 = d_scale[slayer][c0],  sc1 = d_scale[slayer][c0 + 1];
    float sf0 = d_shift[slayer][c0],  sf1 = d_shift[slayer][c0 + 1];
    int node0 = blockIdx.x * 256 + wrp * 32;
    #pragma unroll 1
    for (int i = 0; i < 32; i++) {
        int node = node0 + i;
        if (node >= n) break;
        int rs = d_rowstart[node];
        int re = rs + d_cnt[node];
        float a0 = 0.f, a1 = 0.f;
        int j = rs;
        for (; j + 4 <= re; j += 4) {
            int2 e0 = d_edge[j];
            int2 e1 = d_edge[j + 1];
            int2 e2 = d_edge[j + 2];
            int2 e3 = d_edge[j + 3];
            float2 v0 = *(const float2*)(in + (size_t)e0.x * D + c0);
            float2 v1 = *(const float2*)(in + (size_t)e1.x * D + c0);
            float2 v2 = *(const float2*)(in + (size_t)e2.x * D + c0);
            float2 v3 = *(const float2*)(in + (size_t)e3.x * D + c0);
            float w0 = __int_as_float(e0.y), w1 = __int_as_float(e1.y);
            float w2 = __int_as_float(e2.y), w3 = __int_as_float(e3.y);
            v0.x = fmaxf(fmaf(v0.x, sc0, sf0), 0.f); v0.y = fmaxf(fmaf(v0.y, sc1, sf1), 0.f);
            v1.x = fmaxf(fmaf(v1.x, sc0, sf0), 0.f); v1.y = fmaxf(fmaf(v1.y, sc1, sf1), 0.f);
            v2.x = fmaxf(fmaf(v2.x, sc0, sf0), 0.f); v2.y = fmaxf(fmaf(v2.y, sc1, sf1), 0.f);
            v3.x = fmaxf(fmaf(v3.x, sc0, sf0), 0.f); v3.y = fmaxf(fmaf(v3.y, sc1, sf1), 0.f);
            a0 = fmaf(w0, v0.x, a0); a1 = fmaf(w0, v0.y, a1);
            a0 = fmaf(w1, v1.x, a0); a1 = fmaf(w1, v1.y, a1);
            a0 = fmaf(w2, v2.x, a0); a1 = fmaf(w2, v2.y, a1);
            a0 = fmaf(w3, v3.x, a0); a1 = fmaf(w3, v3.y, a1);
        }
        for (; j < re; j++) {
            int2 e0 = d_edge[j];
            float w0 = __int_as_float(e0.y);
            float2 v0 = *(const float2*)(in + (size_t)e0.x * D + c0);
            v0.x = fmaxf(fmaf(v0.x, sc0, sf0), 0.f);
            v0.y = fmaxf(fmaf(v0.y, sc1, sf1), 0.f);
            a0 = fmaf(w0, v0.x, a0);
            a1 = fmaf(w0, v0.y, a1);
        }
        *(float2*)(d_p + (size_t)node * D + c0) = make_float2(a0, a1);
    }
}

// ------------------- fused node GEMM (f32x2 over column pairs) + fused BN stats ----------
__device__ __forceinline__ void node_fetch(
    int ch, const float* __restrict__ in,
    const float* __restrict__ W1, const float* __restrict__ W2, const float* __restrict__ W3,
    int ln, bool lvalid, float dw, int slayer,
    float lv[KC], float& lw0, float& lw1)
{
    int seg = ch >> 3;
    int kk0 = (ch & 7) * KC;
    const float* W = (seg == 0) ? W1 : ((seg == 1) ? W3 : W2);
    float2 wv = *(const float2*)(W + kk0 * D + threadIdx.x * 2);
    lw0 = wv.x; lw1 = wv.y;
    if (lvalid) {
        const float* row = (seg == 0) ? (d_p + (size_t)ln * D + kk0)
                                      : (in  + (size_t)ln * D + kk0);
        float4 r0 = *(const float4*)(row);
        float4 r1 = *(const float4*)(row + 4);
        lv[0] = r0.x; lv[1] = r0.y; lv[2] = r0.z; lv[3] = r0.w;
        lv[4] = r1.x; lv[5] = r1.y; lv[6] = r1.z; lv[7] = r1.w;
        if (seg >= 1) {
            float4 s0 = *(const float4*)(&d_scale[slayer][kk0]);
            float4 s1 = *(const float4*)(&d_scale[slayer][kk0 + 4]);
            float4 f0 = *(const float4*)(&d_shift[slayer][kk0]);
            float4 f1 = *(const float4*)(&d_shift[slayer][kk0 + 4]);
            lv[0] = fmaxf(fmaf(lv[0], s0.x, f0.x), 0.f);
            lv[1] = fmaxf(fmaf(lv[1], s0.y, f0.y), 0.f);
            lv[2] = fmaxf(fmaf(lv[2], s0.z, f0.z), 0.f);
            lv[3] = fmaxf(fmaf(lv[3], s0.w, f0.w), 0.f);
            lv[4] = fmaxf(fmaf(lv[4], s1.x, f1.x), 0.f);
            lv[5] = fmaxf(fmaf(lv[5], s1.y, f1.y), 0.f);
            lv[6] = fmaxf(fmaf(lv[6], s1.z, f1.z), 0.f);
            lv[7] = fmaxf(fmaf(lv[7], s1.w, f1.w), 0.f);
            if (seg == 2) {
                #pragma unroll
                for (int i = 0; i < KC; i++) lv[i] *= -dw;
            }
        }
    } else {
        #pragma unroll
        for (int i = 0; i < KC; i++) lv[i] = 0.f;
    }
}

__global__ void __launch_bounds__(256) k_node(
    int insel, int slayer,
    const float* __restrict__ W1, const float* __restrict__ b1,
    const float* __restrict__ W2, const float* __restrict__ W3,
    const float* __restrict__ b3,
    int outsel, int n)
{
    __shared__ __align__(16) float in_s[2][KC][256];
    __shared__ __align__(16) float w_s[2][KC][D];
    __shared__ __align__(16) float bns[32][D + 1];
    __shared__ __align__(16) float bnq[32][D + 1];
    const float* __restrict__ in = nodebuf(insel);
    float* __restrict__ y = nodebuf(outsel);
    int t = threadIdx.x;
    int node0 = blockIdx.x * 256;
    int ln = node0 + t;
    bool lvalid = ln < n;
    float dw = lvalid ? d_degw[ln] : 0.f;
    int tc = t & 7;
    int tr = t >> 3;

    unsigned long long acc2[8][4];
    #pragma unroll
    for (int i = 0; i < 8; i++)
        #pragma unroll
        for (int j = 0; j < 4; j++) acc2[i][j] = 0ull;

    float lv[KC]; float lw0, lw1;
    node_fetch(0, in, W1, W2, W3, ln, lvalid, dw, slayer, lv, lw0, lw1);

    const int NCH = (3 * D) / KC;
    for (int ch = 0; ch < NCH; ch++) {
        int b = ch & 1;
        *((float2*)(&w_s[b][0][0]) + t) = make_float2(lw0, lw1);
        #pragma unroll
        for (int i = 0; i < KC; i++) in_s[b][i][t] = lv[i];
        __syncthreads();
        if (ch + 1 < NCH)
            node_fetch(ch + 1, in, W1, W2, W3, ln, lvalid, dw, slayer, lv, lw0, lw1);
        #pragma unroll
        for (int kk = 0; kk < KC; kk++) {
            float4 ia = *(const float4*)&in_s[b][kk][tr * 8];
            float4 ib = *(const float4*)&in_s[b][kk][tr * 8 + 4];
            ulonglong2 wa = *(const ulonglong2*)&w_s[b][kk][tc * 8];
            ulonglong2 wb = *(const ulonglong2*)&w_s[b][kk][tc * 8 + 4];
            unsigned long long wv[4] = {wa.x, wa.y, wb.x, wb.y};
            unsigned long long dv[8];
            dv[0] = dup2(ia.x); dv[1] = dup2(ia.y); dv[2] = dup2(ia.z); dv[3] = dup2(ia.w);
            dv[4] = dup2(ib.x); dv[5] = dup2(ib.y); dv[6] = dup2(ib.z); dv[7] = dup2(ib.w);
            #pragma unroll
            for (int i = 0; i < 8; i++)
                #pragma unroll
                for (int j = 0; j < 4; j++)
                    fma2(acc2[i][j], dv[i], wv[j]);
        }
        __syncthreads();
    }

    float4 b1a = *(const float4*)(b1 + tc * 8);
    float4 b1b = *(const float4*)(b1 + tc * 8 + 4);
    float4 b3a = *(const float4*)(b3 + tc * 8);
    float4 b3b = *(const float4*)(b3 + tc * 8 + 4);
    float bb1[8] = {b1a.x, b1a.y, b1a.z, b1a.w, b1b.x, b1b.y, b1b.z, b1b.w};
    float bb3[8] = {b3a.x, b3a.y, b3a.z, b3a.w, b3b.x, b3b.y, b3b.z, b3b.w};
    float s_acc[8], q_acc[8];
    #pragma unroll
    for (int j = 0; j < 8; j++) { s_acc[j] = 0.f; q_acc[j] = 0.f; }
    union cvu { unsigned long long u; float2 f; };
    #pragma unroll
    for (int i = 0; i < 8; i++) {
        int node = node0 + tr * 8 + i;
        if (node < n) {
            float dwn = d_degw[node];
            float o[8];
            #pragma unroll
            for (int jp = 0; jp < 4; jp++) {
                cvu cv; cv.u = acc2[i][jp];
                o[jp * 2]     = cv.f.x + fmaf(dwn, bb1[jp * 2],     bb3[jp * 2]);
                o[jp * 2 + 1] = cv.f.y + fmaf(dwn, bb1[jp * 2 + 1], bb3[jp * 2 + 1]);
            }
            #pragma unroll
            for (int j = 0; j < 8; j++) {
                s_acc[j] += o[j];
                q_acc[j] = fmaf(o[j], o[j], q_acc[j]);
            }
            float* yp = y + (size_t)node * D + tc * 8;
            *(float4*)(yp)     = make_float4(o[0], o[1], o[2], o[3]);
            *(float4*)(yp + 4) = make_float4(o[4], o[5], o[6], o[7]);
        }
    }
    #pragma unroll
    for (int j = 0; j < 8; j++) {
        bns[tr][tc * 8 + j] = s_acc[j];
        bnq[tr][tc * 8 + j] = q_acc[j];
    }
    __syncthreads();
    if (t < D) {
        float s = 0.f, q = 0.f;
        #pragma unroll
        for (int r = 0; r < 32; r++) { s += bns[r][t]; q += bnq[r][t]; }
        d_bnpart_s[blockIdx.x][t] = s;
        d_bnpart_q[blockIdx.x][t] = q;
    }
}

// ------------------- BN finalize (parallel fp64 reduction) -------------------
__global__ void __launch_bounds__(512) k_bn_final(int layer, const float* __restrict__ gamma,
                                                  const float* __restrict__ beta,
                                                  int n, int nblocks) {
    __shared__ double sh_s[8][D];
    __shared__ double sh_q[8][D];
    int t = threadIdx.x;
    int c = t & 63;
    int ck = t >> 6;
    double s = 0.0, q = 0.0;
    for (int b = ck; b < nblocks; b += 8) {
        s += (double)d_bnpart_s[b][c];
        q += (double)d_bnpart_q[b][c];
    }
    sh_s[ck][c] = s;
    sh_q[ck][c] = q;
    __syncthreads();
    if (t < D) {
        double ss = 0.0, qq = 0.0;
        #pragma unroll
        for (int r = 0; r < 8; r++) { ss += sh_s[r][t]; qq += sh_q[r][t]; }
        double m   = ss / (double)n;
        double var = qq / (double)n - m * m;
        if (var < 0.0) var = 0.0;
        float sc = gamma[layer * D + t] * rsqrtf((float)var + BNEPS);
        d_scale[layer][t] = sc;
        d_shift[layer][t] = beta[layer * D + t] - (float)m * sc;
    }
}

// ------------------- fused pooling + MLP head (BN2+relu applied on the fly) --------------
__global__ void __launch_bounds__(512) k_poolhead(
    int ysel, int slayer,
    const float* __restrict__ Wl1, const float* __restrict__ bl1,
    const float* __restrict__ Wl2, const float* __restrict__ bl2,
    float* __restrict__ out, int n)
{
    const float* __restrict__ y = nodebuf(ysel);
    __shared__ float red[512];
    __shared__ float gr[D];
    __shared__ float hid[D];
    int g = blockIdx.x;
    int s = d_goff[g], e = d_goff[g + 1];
    int t = threadIdx.x;
    int c = t & 63, rl = t >> 6;
    float sc = d_scale[slayer][c], sf = d_shift[slayer][c];
    float acc = 0.f;
    for (int r = s + rl; r < e; r += 8)
        acc += fmaxf(fmaf(y[(size_t)r * D + c], sc, sf), 0.f);
    red[t] = acc;
    __syncthreads();
    if (t < D) {
        float tot = 0.f;
        #pragma unroll
        for (int r = 0; r < 8; r++) tot += red[r * 64 + t];
        float cnt = (float)(e - s);
        if (cnt < 1.f) cnt = 1.f;
        gr[t] = tot / cnt;
    }
    __syncthreads();
    if (t < D) {
        float a = bl1[t];
        #pragma unroll
        for (int k = 0; k < D; k++) a = fmaf(gr[k], Wl1[k * D + t], a);
        hid[t] = fmaxf(a, 0.f);
    }
    __syncthreads();
    if (t < 3) {
        float o = bl2[t];
        #pragma unroll
        for (int k = 0; k < D; k++) o = fmaf(hid[k], Wl2[k * 3 + t], o);
        out[g * 3 + t] = o;
    }
}

// ------------------- launch -------------------
extern "C" void kernel_launch(void* const* d_in, const int* in_sizes, int n_in,
                              void* d_out, int out_size) {
    const float* x     = (const float*)d_in[0];
    const int*   eid   = (const int*)d_in[1];
    const float* attr  = (const float*)d_in[2];
    const int*   batch = (const int*)d_in[3];
    const float* W_emb = (const float*)d_in[4];
    const float* b_emb = (const float*)d_in[5];
    const float* W1    = (const float*)d_in[6];
    const float* b1    = (const float*)d_in[7];
    const float* W2    = (const float*)d_in[8];
    const float* W3    = (const float*)d_in[9];
    const float* b3    = (const float*)d_in[10];
    const float* gamma = (const float*)d_in[11];
    const float* beta  = (const float*)d_in[12];
    const float* Wl1   = (const float*)d_in[13];
    const float* bl1   = (const float*)d_in[14];
    const float* Wl2   = (const float*)d_in[15];
    const float* bl2   = (const float*)d_in[16];

    int N = in_sizes[0] / 4;
    int E = in_sizes[1] / 2;

    k_zero<<<(N + 255) / 256, 256>>>(W_emb, b_emb, W1, b1, W2, W3, b3, N);
    k_epass1<<<(E + 255) / 256, 256>>>(eid, batch, E, N);
    k_goff<<<1, GMAX>>>();
    int nb = (N + 4095) / 4096;
    k_scan1<<<nb, 256>>>(N);
    k_scan2<<<1, 256>>>(nb);
    k_scan3<<<(N + 255) / 256, 256>>>(N);
    k_epass2<<<(E + 255) / 256, 256>>>(eid, attr, E);

    int NB = (N + 255) / 256;

    // layer 0 (folded through embedding; fused gather + combine + degw)
    k_layer0<<<NB, 256>>>(x, gamma, beta, N);
    k_bn_final<<<1, 512>>>(0, gamma, beta, N, NB);

    // layer 1
    k_edge_agg<<<NB, 256>>>(1, 0, N);
    k_node<<<NB, 256>>>(1, 0, W1 + 4096, b1 + 64, W2 + 4096, W3 + 4096, b3 + 64, 2, N);
    k_bn_final<<<1, 512>>>(1, gamma, beta, N, NB);

    // layer 2
    k_edge_agg<<<NB, 256>>>(2, 1, N);
    k_node<<<NB, 256>>>(2, 1, W1 + 8192, b1 + 128, W2 + 8192, W3 + 8192, b3 + 128, 1, N);
    k_bn_final<<<1, 512>>>(2, gamma, beta, N, NB);

    // pooling (BN2+relu fused) + head
    k_poolhead<<<GMAX, 512>>>(1, 2, Wl1, bl1, Wl2, bl2, (float*)d_out, N);
}

// round 14
// speedup vs baseline: 1.1618x; 1.1618x over previous
#include <cuda_runtime.h>
#include <math.h>
#include <cstdint>

#define D 64
#define GMAX 256
#define N_MAX 100000
#define E_MAX 1200000
#define KC 8
#define BNEPS 1e-5f
#define NB_MAX 400

// ------------------- scratch (static device globals; no allocation) -------------------
__device__ __align__(16) float d_ya[(size_t)N_MAX * D];
__device__ __align__(16) float d_yb[(size_t)N_MAX * D];
__device__ __align__(16) float d_p [(size_t)N_MAX * D];
__device__ float d_degw[N_MAX];
__device__ int   d_cnt[N_MAX];
__device__ int   d_fill[N_MAX];
__device__ int   d_rowstart[N_MAX];
__device__ int   d_blksum[128];
__device__ __align__(16) int2 d_edge[E_MAX];   // (src, attr bits)
__device__ int   d_gcount[GMAX];
__device__ int   d_goff[GMAX + 1];
__device__ float d_bnpart_s[NB_MAX][D];
__device__ float d_bnpart_q[NB_MAX][D];
__device__ __align__(16) float d_scale[3][D];
__device__ __align__(16) float d_shift[3][D];
// folded layer-0 params
__device__ __align__(16) float d_M1[4 * D];
__device__ __align__(16) float d_M2[4 * D];
__device__ __align__(16) float d_M3[4 * D];
__device__ __align__(16) float d_u[D];
__device__ __align__(16) float d_v[D];

__device__ __forceinline__ float* nodebuf(int s) {
    return (s == 1) ? d_ya : d_yb;
}

// packed fp32x2 FMA (sm_100+)
__device__ __forceinline__ void fma2(unsigned long long& d,
                                     unsigned long long a,
                                     unsigned long long b) {
    asm("fma.rn.f32x2 %0, %1, %2, %0;" : "+l"(d) : "l"(a), "l"(b));
}
__device__ __forceinline__ unsigned long long dup2(float v) {
    unsigned long long d;
    int b = __float_as_int(v);
    asm("mov.b64 %0, {%1, %2};" : "=l"(d) : "r"(b), "r"(b));
    return d;
}

// ------------------- init + folded layer-0 param prep -------------------
__global__ void k_zero(const float* __restrict__ W_emb, const float* __restrict__ b_emb,
                       const float* __restrict__ W1, const float* __restrict__ b1,
                       const float* __restrict__ W2, const float* __restrict__ W3,
                       const float* __restrict__ b3, int n) {
    int i = blockIdx.x * blockDim.x + threadIdx.x;
    if (i < n) d_cnt[i] = 0;
    if (i < GMAX) d_gcount[i] = 0;
    if (blockIdx.x == 0) {
        int t = threadIdx.x;
        int j = t >> 6, c = t & 63;
        float a1 = 0.f, a2 = 0.f, a3 = 0.f;
        #pragma unroll 4
        for (int k = 0; k < 64; k++) {
            float we = W_emb[j * 64 + k];
            a1 = fmaf(we, W1[k * 64 + c], a1);
            a2 = fmaf(we, W2[k * 64 + c], a2);
            a3 = fmaf(we, W3[k * 64 + c], a3);
        }
        d_M1[j * 64 + c] = a1;
        d_M2[j * 64 + c] = a2;
        d_M3[j * 64 + c] = a3;
        if (t < 64) {
            float u = b1[t], v = b3[t];
            #pragma unroll 4
            for (int k = 0; k < 64; k++) {
                float be = b_emb[k];
                u = fmaf(be, W1[k * 64 + t] - W2[k * 64 + t], u);
                v = fmaf(be, W3[k * 64 + t], v);
            }
            d_u[t] = u;
            d_v[t] = v;
        }
    }
}

// ------------------- CSR build pass 1 + graph histogram -------------------
__global__ void k_epass1(const int* __restrict__ eid, const int* __restrict__ batch,
                         int E, int N) {
    int e = blockIdx.x * blockDim.x + threadIdx.x;
    if (e < E) atomicAdd(&d_cnt[eid[(size_t)E + e]], 1);
    if (e < N) atomicAdd(&d_gcount[batch[e]], 1);
}

__global__ void k_goff() {
    __shared__ int sh[GMAX];
    int t = threadIdx.x;
    int v = d_gcount[t];
    sh[t] = v; __syncthreads();
    for (int off = 1; off < GMAX; off <<= 1) {
        int add = (t >= off) ? sh[t - off] : 0;
        __syncthreads();
        sh[t] += add;
        __syncthreads();
    }
    d_goff[t + 1] = sh[t];
    if (t == 0) d_goff[0] = 0;
}

// 4 elements per thread, 1024 per block -> 98 blocks for N=100k
__global__ void k_scan1(int n) {
    __shared__ int sh[256];
    int t = threadIdx.x;
    int base = blockIdx.x * 1024 + t * 4;
    int v[4]; int tot = 0;
    #pragma unroll
    for (int i = 0; i < 4; i++) {
        int idx = base + i;
        v[i] = (idx < n) ? d_cnt[idx] : 0;
        tot += v[i];
    }
    sh[t] = tot; __syncthreads();
    for (int off = 1; off < 256; off <<= 1) {
        int add = (t >= off) ? sh[t - off] : 0;
        __syncthreads();
        sh[t] += add;
        __syncthreads();
    }
    int run = sh[t] - tot;
    #pragma unroll
    for (int i = 0; i < 4; i++) {
        int idx = base + i;
        if (idx < n) d_rowstart[idx] = run;
        run += v[i];
    }
    if (t == 255) d_blksum[blockIdx.x] = sh[255];
}

__global__ void k_scan2(int nb) {
    __shared__ int sh[256];
    int t = threadIdx.x;
    int v = (t < nb) ? d_blksum[t] : 0;
    sh[t] = v; __syncthreads();
    for (int off = 1; off < 256; off <<= 1) {
        int add = (t >= off) ? sh[t - off] : 0;
        __syncthreads();
        sh[t] += add;
        __syncthreads();
    }
    if (t < nb) d_blksum[t] = sh[t] - v;
}

__global__ void k_scan3(int n) {
    int i = blockIdx.x * blockDim.x + threadIdx.x;
    if (i < n) {
        int rs = d_rowstart[i] + d_blksum[i >> 10];
        d_rowstart[i] = rs;
        d_fill[i] = rs;
    }
}

__global__ void k_epass2(const int* __restrict__ eid, const float* __restrict__ attr, int E) {
    int e = blockIdx.x * blockDim.x + threadIdx.x;
    if (e >= E) return;
    int s  = eid[e];
    int dd = eid[(size_t)E + e];
    int pos = atomicAdd(&d_fill[dd], 1);
    d_edge[pos] = make_int2(s, __float_as_int(attr[e]));
}

// ---------- folded layer 0 (fused x-gather + combine) + BN stats; writes degw ----------
__global__ void __launch_bounds__(256) k_layer0(const float* __restrict__ x,
                                                const float* __restrict__ gamma,
                                                const float* __restrict__ beta, int n) {
    __shared__ __align__(16) float g_s[256][5];     // g[4] + degw per node
    __shared__ __align__(16) float bns[8][D + 1];
    __shared__ __align__(16) float bnq[8][D + 1];
    int t = threadIdx.x;
    int node0b = blockIdx.x * 256;
    float* __restrict__ y = d_ya;

    // phase 1: thread-per-node gather of x rows + degw (CSR row sum)
    {
        int node = node0b + t;
        float g0 = 0.f, g1 = 0.f, g2 = 0.f, g3 = 0.f, sw = 0.f;
        if (node < n) {
            int rs = d_rowstart[node];
            int re = rs + d_cnt[node];
            int j = rs;
            for (; j + 2 <= re; j += 2) {
                int2 e0 = d_edge[j];
                int2 e1 = d_edge[j + 1];
                float4 x0 = *(const float4*)(x + (size_t)e0.x * 4);
                float4 x1 = *(const float4*)(x + (size_t)e1.x * 4);
                float w0 = __int_as_float(e0.y), w1 = __int_as_float(e1.y);
                g0 = fmaf(w0, x0.x, g0); g1 = fmaf(w0, x0.y, g1);
                g2 = fmaf(w0, x0.z, g2); g3 = fmaf(w0, x0.w, g3);
                g0 = fmaf(w1, x1.x, g0); g1 = fmaf(w1, x1.y, g1);
                g2 = fmaf(w1, x1.z, g2); g3 = fmaf(w1, x1.w, g3);
                sw += w0 + w1;
            }
            if (j < re) {
                int2 e0 = d_edge[j];
                float4 x0 = *(const float4*)(x + (size_t)e0.x * 4);
                float w0 = __int_as_float(e0.y);
                g0 = fmaf(w0, x0.x, g0); g1 = fmaf(w0, x0.y, g1);
                g2 = fmaf(w0, x0.z, g2); g3 = fmaf(w0, x0.w, g3);
                sw += w0;
            }
            d_degw[node] = sw;
        }
        g_s[t][0] = g0; g_s[t][1] = g1; g_s[t][2] = g2; g_s[t][3] = g3; g_s[t][4] = sw;
    }
    __syncthreads();

    // phase 2: combine (lane = channel pair; warp covers 32 nodes)
    int cp = t & 31;
    int c0 = cp * 2;
    int wrp = t >> 5;
    int node0 = node0b + wrp * 32;

    float2 m1[4], m2[4], m3[4];
    #pragma unroll
    for (int k = 0; k < 4; k++) {
        m1[k] = *(const float2*)(d_M1 + k * 64 + c0);
        m2[k] = *(const float2*)(d_M2 + k * 64 + c0);
        m3[k] = *(const float2*)(d_M3 + k * 64 + c0);
    }
    float2 uv = *(const float2*)(d_u + c0);
    float2 vv = *(const float2*)(d_v + c0);

    float s0 = 0.f, s1 = 0.f, q0 = 0.f, q1 = 0.f;
    #pragma unroll 2
    for (int i = 0; i < 32; i++) {
        int node = node0 + i;
        if (node < n) {
            int lr = wrp * 32 + i;
            float gx = g_s[lr][0], gy = g_s[lr][1], gz = g_s[lr][2], gw = g_s[lr][3];
            float dwn = g_s[lr][4];
            float4 xr = *(const float4*)(x + (size_t)node * 4);
            float o0 = fmaf(dwn, uv.x, vv.x);
            float o1 = fmaf(dwn, uv.y, vv.y);
            o0 = fmaf(gx, m1[0].x, o0); o1 = fmaf(gx, m1[0].y, o1);
            o0 = fmaf(gy, m1[1].x, o0); o1 = fmaf(gy, m1[1].y, o1);
            o0 = fmaf(gz, m1[2].x, o0); o1 = fmaf(gz, m1[2].y, o1);
            o0 = fmaf(gw, m1[3].x, o0); o1 = fmaf(gw, m1[3].y, o1);
            float w20 = xr.x * m2[0].x, w21 = xr.x * m2[0].y;
            w20 = fmaf(xr.y, m2[1].x, w20); w21 = fmaf(xr.y, m2[1].y, w21);
            w20 = fmaf(xr.z, m2[2].x, w20); w21 = fmaf(xr.z, m2[2].y, w21);
            w20 = fmaf(xr.w, m2[3].x, w20); w21 = fmaf(xr.w, m2[3].y, w21);
            o0 = fmaf(-dwn, w20, o0);
            o1 = fmaf(-dwn, w21, o1);
            o0 = fmaf(xr.x, m3[0].x, o0); o1 = fmaf(xr.x, m3[0].y, o1);
            o0 = fmaf(xr.y, m3[1].x, o0); o1 = fmaf(xr.y, m3[1].y, o1);
            o0 = fmaf(xr.z, m3[2].x, o0); o1 = fmaf(xr.z, m3[2].y, o1);
            o0 = fmaf(xr.w, m3[3].x, o0); o1 = fmaf(xr.w, m3[3].y, o1);
            *(float2*)(y + (size_t)node * D + c0) = make_float2(o0, o1);
            s0 += o0; s1 += o1;
            q0 = fmaf(o0, o0, q0);
            q1 = fmaf(o1, o1, q1);
        }
    }
    bns[wrp][c0] = s0; bns[wrp][c0 + 1] = s1;
    bnq[wrp][c0] = q0; bnq[wrp][c0 + 1] = q1;
    __syncthreads();
    if (t < D) {
        float s = 0.f, q = 0.f;
        #pragma unroll
        for (int r = 0; r < 8; r++) { s += bns[r][t]; q += bnq[r][t]; }
        d_bnpart_s[blockIdx.x][t] = s;
        d_bnpart_q[blockIdx.x][t] = q;
    }
}

// ------------------- edge aggregation: p[i] = sum attr_e * hin[src_e] -------------------
// warp per node (8 nodes/block), unroll-4 -> MLP 4; 100k warps hide L2 latency.
__global__ void k_edge_agg(int insel, int slayer, int n) {
    int node = blockIdx.x * 8 + (threadIdx.x >> 5);
    if (node >= n) return;
    const float* __restrict__ in = nodebuf(insel);
    int lane = threadIdx.x & 31;
    int c0 = lane * 2;
    float sc0 = d_scale[slayer][c0],  sc1 = d_scale[slayer][c0 + 1];
    float sf0 = d_shift[slayer][c0],  sf1 = d_shift[slayer][c0 + 1];
    int rs = d_rowstart[node];
    int re = rs + d_cnt[node];
    float a0 = 0.f, a1 = 0.f;
    int j = rs;
    for (; j + 4 <= re; j += 4) {
        int2 e0 = d_edge[j];
        int2 e1 = d_edge[j + 1];
        int2 e2 = d_edge[j + 2];
        int2 e3 = d_edge[j + 3];
        float2 v0 = *(const float2*)(in + (size_t)e0.x * D + c0);
        float2 v1 = *(const float2*)(in + (size_t)e1.x * D + c0);
        float2 v2 = *(const float2*)(in + (size_t)e2.x * D + c0);
        float2 v3 = *(const float2*)(in + (size_t)e3.x * D + c0);
        float w0 = __int_as_float(e0.y), w1 = __int_as_float(e1.y);
        float w2 = __int_as_float(e2.y), w3 = __int_as_float(e3.y);
        v0.x = fmaxf(fmaf(v0.x, sc0, sf0), 0.f); v0.y = fmaxf(fmaf(v0.y, sc1, sf1), 0.f);
        v1.x = fmaxf(fmaf(v1.x, sc0, sf0), 0.f); v1.y = fmaxf(fmaf(v1.y, sc1, sf1), 0.f);
        v2.x = fmaxf(fmaf(v2.x, sc0, sf0), 0.f); v2.y = fmaxf(fmaf(v2.y, sc1, sf1), 0.f);
        v3.x = fmaxf(fmaf(v3.x, sc0, sf0), 0.f); v3.y = fmaxf(fmaf(v3.y, sc1, sf1), 0.f);
        a0 = fmaf(w0, v0.x, a0); a1 = fmaf(w0, v0.y, a1);
        a0 = fmaf(w1, v1.x, a0); a1 = fmaf(w1, v1.y, a1);
        a0 = fmaf(w2, v2.x, a0); a1 = fmaf(w2, v2.y, a1);
        a0 = fmaf(w3, v3.x, a0); a1 = fmaf(w3, v3.y, a1);
    }
    for (; j < re; j++) {
        int2 e0 = d_edge[j];
        float w0 = __int_as_float(e0.y);
        float2 v0 = *(const float2*)(in + (size_t)e0.x * D + c0);
        v0.x = fmaxf(fmaf(v0.x, sc0, sf0), 0.f);
        v0.y = fmaxf(fmaf(v0.y, sc1, sf1), 0.f);
        a0 = fmaf(w0, v0.x, a0);
        a1 = fmaf(w0, v0.y, a1);
    }
    *(float2*)(d_p + (size_t)node * D + c0) = make_float2(a0, a1);
}

// ------------------- fused node GEMM (f32x2 over column pairs) + fused BN stats ----------
__device__ __forceinline__ void node_fetch(
    int ch, const float* __restrict__ in,
    const float* __restrict__ W1, const float* __restrict__ W2, const float* __restrict__ W3,
    int ln, bool lvalid, float dw, int slayer,
    float lv[KC], float& lw0, float& lw1)
{
    int seg = ch >> 3;
    int kk0 = (ch & 7) * KC;
    const float* W = (seg == 0) ? W1 : ((seg == 1) ? W3 : W2);
    float2 wv = *(const float2*)(W + kk0 * D + threadIdx.x * 2);
    lw0 = wv.x; lw1 = wv.y;
    if (lvalid) {
        const float* row = (seg == 0) ? (d_p + (size_t)ln * D + kk0)
                                      : (in  + (size_t)ln * D + kk0);
        float4 r0 = *(const float4*)(row);
        float4 r1 = *(const float4*)(row + 4);
        lv[0] = r0.x; lv[1] = r0.y; lv[2] = r0.z; lv[3] = r0.w;
        lv[4] = r1.x; lv[5] = r1.y; lv[6] = r1.z; lv[7] = r1.w;
        if (seg >= 1) {
            float4 s0 = *(const float4*)(&d_scale[slayer][kk0]);
            float4 s1 = *(const float4*)(&d_scale[slayer][kk0 + 4]);
            float4 f0 = *(const float4*)(&d_shift[slayer][kk0]);
            float4 f1 = *(const float4*)(&d_shift[slayer][kk0 + 4]);
            lv[0] = fmaxf(fmaf(lv[0], s0.x, f0.x), 0.f);
            lv[1] = fmaxf(fmaf(lv[1], s0.y, f0.y), 0.f);
            lv[2] = fmaxf(fmaf(lv[2], s0.z, f0.z), 0.f);
            lv[3] = fmaxf(fmaf(lv[3], s0.w, f0.w), 0.f);
            lv[4] = fmaxf(fmaf(lv[4], s1.x, f1.x), 0.f);
            lv[5] = fmaxf(fmaf(lv[5], s1.y, f1.y), 0.f);
            lv[6] = fmaxf(fmaf(lv[6], s1.z, f1.z), 0.f);
            lv[7] = fmaxf(fmaf(lv[7], s1.w, f1.w), 0.f);
            if (seg == 2) {
                #pragma unroll
                for (int i = 0; i < KC; i++) lv[i] *= -dw;
            }
        }
    } else {
        #pragma unroll
        for (int i = 0; i < KC; i++) lv[i] = 0.f;
    }
}

__global__ void __launch_bounds__(256) k_node(
    int insel, int slayer,
    const float* __restrict__ W1, const float* __restrict__ b1,
    const float* __restrict__ W2, const float* __restrict__ W3,
    const float* __restrict__ b3,
    int outsel, int n)
{
    __shared__ __align__(16) float in_s[2][KC][256];
    __shared__ __align__(16) float w_s[2][KC][D];
    __shared__ __align__(16) float bns[32][D + 1];
    __shared__ __align__(16) float bnq[32][D + 1];
    const float* __restrict__ in = nodebuf(insel);
    float* __restrict__ y = nodebuf(outsel);
    int t = threadIdx.x;
    int node0 = blockIdx.x * 256;
    int ln = node0 + t;
    bool lvalid = ln < n;
    float dw = lvalid ? d_degw[ln] : 0.f;
    int tc = t & 7;
    int tr = t >> 3;

    unsigned long long acc2[8][4];
    #pragma unroll
    for (int i = 0; i < 8; i++)
        #pragma unroll
        for (int j = 0; j < 4; j++) acc2[i][j] = 0ull;

    float lv[KC]; float lw0, lw1;
    node_fetch(0, in, W1, W2, W3, ln, lvalid, dw, slayer, lv, lw0, lw1);

    const int NCH = (3 * D) / KC;
    for (int ch = 0; ch < NCH; ch++) {
        int b = ch & 1;
        *((float2*)(&w_s[b][0][0]) + t) = make_float2(lw0, lw1);
        #pragma unroll
        for (int i = 0; i < KC; i++) in_s[b][i][t] = lv[i];
        __syncthreads();
        if (ch + 1 < NCH)
            node_fetch(ch + 1, in, W1, W2, W3, ln, lvalid, dw, slayer, lv, lw0, lw1);
        #pragma unroll
        for (int kk = 0; kk < KC; kk++) {
            float4 ia = *(const float4*)&in_s[b][kk][tr * 8];
            float4 ib = *(const float4*)&in_s[b][kk][tr * 8 + 4];
            ulonglong2 wa = *(const ulonglong2*)&w_s[b][kk][tc * 8];
            ulonglong2 wb = *(const ulonglong2*)&w_s[b][kk][tc * 8 + 4];
            unsigned long long wv[4] = {wa.x, wa.y, wb.x, wb.y};
            unsigned long long dv[8];
            dv[0] = dup2(ia.x); dv[1] = dup2(ia.y); dv[2] = dup2(ia.z); dv[3] = dup2(ia.w);
            dv[4] = dup2(ib.x); dv[5] = dup2(ib.y); dv[6] = dup2(ib.z); dv[7] = dup2(ib.w);
            #pragma unroll
            for (int i = 0; i < 8; i++)
                #pragma unroll
                for (int j = 0; j < 4; j++)
                    fma2(acc2[i][j], dv[i], wv[j]);
        }
        __syncthreads();
    }

    float4 b1a = *(const float4*)(b1 + tc * 8);
    float4 b1b = *(const float4*)(b1 + tc * 8 + 4);
    float4 b3a = *(const float4*)(b3 + tc * 8);
    float4 b3b = *(const float4*)(b3 + tc * 8 + 4);
    float bb1[8] = {b1a.x, b1a.y, b1a.z, b1a.w, b1b.x, b1b.y, b1b.z, b1b.w};
    float bb3[8] = {b3a.x, b3a.y, b3a.z, b3a.w, b3b.x, b3b.y, b3b.z, b3b.w};
    float s_acc[8], q_acc[8];
    #pragma unroll
    for (int j = 0; j < 8; j++) { s_acc[j] = 0.f; q_acc[j] = 0.f; }
    union cvu { unsigned long long u; float2 f; };
    #pragma unroll
    for (int i = 0; i < 8; i++) {
        int node = node0 + tr * 8 + i;
        if (node < n) {
            float dwn = d_degw[node];
            float o[8];
            #pragma unroll
            for (int jp = 0; jp < 4; jp++) {
                cvu cv; cv.u = acc2[i][jp];
                o[jp * 2]     = cv.f.x + fmaf(dwn, bb1[jp * 2],     bb3[jp * 2]);
                o[jp * 2 + 1] = cv.f.y + fmaf(dwn, bb1[jp * 2 + 1], bb3[jp * 2 + 1]);
            }
            #pragma unroll
            for (int j = 0; j < 8; j++) {
                s_acc[j] += o[j];
                q_acc[j] = fmaf(o[j], o[j], q_acc[j]);
            }
            float* yp = y + (size_t)node * D + tc * 8;
            *(float4*)(yp)     = make_float4(o[0], o[1], o[2], o[3]);
            *(float4*)(yp + 4) = make_float4(o[4], o[5], o[6], o[7]);
        }
    }
    #pragma unroll
    for (int j = 0; j < 8; j++) {
        bns[tr][tc * 8 + j] = s_acc[j];
        bnq[tr][tc * 8 + j] = q_acc[j];
    }
    __syncthreads();
    if (t < D) {
        float s = 0.f, q = 0.f;
        #pragma unroll
        for (int r = 0; r < 32; r++) { s += bns[r][t]; q += bnq[r][t]; }
        d_bnpart_s[blockIdx.x][t] = s;
        d_bnpart_q[blockIdx.x][t] = q;
    }
}

// ------------------- BN finalize (parallel fp64 reduction) -------------------
__global__ void __launch_bounds__(512) k_bn_final(int layer, const float* __restrict__ gamma,
                                                  const float* __restrict__ beta,
                                                  int n, int nblocks) {
    __shared__ double sh_s[8][D];
    __shared__ double sh_q[8][D];
    int t = threadIdx.x;
    int c = t & 63;
    int ck = t >> 6;
    double s = 0.0, q = 0.0;
    for (int b = ck; b < nblocks; b += 8) {
        s += (double)d_bnpart_s[b][c];
        q += (double)d_bnpart_q[b][c];
    }
    sh_s[ck][c] = s;
    sh_q[ck][c] = q;
    __syncthreads();
    if (t < D) {
        double ss = 0.0, qq = 0.0;
        #pragma unroll
        for (int r = 0; r < 8; r++) { ss += sh_s[r][t]; qq += sh_q[r][t]; }
        double m   = ss / (double)n;
        double var = qq / (double)n - m * m;
        if (var < 0.0) var = 0.0;
        float sc = gamma[layer * D + t] * rsqrtf((float)var + BNEPS);
        d_scale[layer][t] = sc;
        d_shift[layer][t] = beta[layer * D + t] - (float)m * sc;
    }
}

// ------------------- fused pooling + MLP head (BN2+relu applied on the fly) --------------
__global__ void __launch_bounds__(512) k_poolhead(
    int ysel, int slayer,
    const float* __restrict__ Wl1, const float* __restrict__ bl1,
    const float* __restrict__ Wl2, const float* __restrict__ bl2,
    float* __restrict__ out, int n)
{
    const float* __restrict__ y = nodebuf(ysel);
    __shared__ float red[512];
    __shared__ float gr[D];
    __shared__ float hid[D];
    int g = blockIdx.x;
    int s = d_goff[g], e = d_goff[g + 1];
    int t = threadIdx.x;
    int c = t & 63, rl = t >> 6;
    float sc = d_scale[slayer][c], sf = d_shift[slayer][c];
    float acc = 0.f;
    for (int r = s + rl; r < e; r += 8)
        acc += fmaxf(fmaf(y[(size_t)r * D + c], sc, sf), 0.f);
    red[t] = acc;
    __syncthreads();
    if (t < D) {
        float tot = 0.f;
        #pragma unroll
        for (int r = 0; r < 8; r++) tot += red[r * 64 + t];
        float cnt = (float)(e - s);
        if (cnt < 1.f) cnt = 1.f;
        gr[t] = tot / cnt;
    }
    __syncthreads();
    if (t < D) {
        float a = bl1[t];
        #pragma unroll
        for (int k = 0; k < D; k++) a = fmaf(gr[k], Wl1[k * D + t], a);
        hid[t] = fmaxf(a, 0.f);
    }
    __syncthreads();
    if (t < 3) {
        float o = bl2[t];
        #pragma unroll
        for (int k = 0; k < D; k++) o = fmaf(hid[k], Wl2[k * 3 + t], o);
        out[g * 3 + t] = o;
    }
}

// ------------------- launch -------------------
extern "C" void kernel_launch(void* const* d_in, const int* in_sizes, int n_in,
                              void* d_out, int out_size) {
    const float* x     = (const float*)d_in[0];
    const int*   eid   = (const int*)d_in[1];
    const float* attr  = (const float*)d_in[2];
    const int*   batch = (const int*)d_in[3];
    const float* W_emb = (const float*)d_in[4];
    const float* b_emb = (const float*)d_in[5];
    const float* W1    = (const float*)d_in[6];
    const float* b1    = (const float*)d_in[7];
    const float* W2    = (const float*)d_in[8];
    const float* W3    = (const float*)d_in[9];
    const float* b3    = (const float*)d_in[10];
    const float* gamma = (const float*)d_in[11];
    const float* beta  = (const float*)d_in[12];
    const float* Wl1   = (const float*)d_in[13];
    const float* bl1   = (const float*)d_in[14];
    const float* Wl2   = (const float*)d_in[15];
    const float* bl2   = (const float*)d_in[16];

    int N = in_sizes[0] / 4;
    int E = in_sizes[1] / 2;

    k_zero<<<(N + 255) / 256, 256>>>(W_emb, b_emb, W1, b1, W2, W3, b3, N);
    k_epass1<<<(E + 255) / 256, 256>>>(eid, batch, E, N);
    int nb = (N + 1023) / 1024;
    k_scan1<<<nb, 256>>>(N);
    k_scan2<<<1, 256>>>(nb);
    k_scan3<<<(N + 255) / 256, 256>>>(N);
    k_epass2<<<(E + 255) / 256, 256>>>(eid, attr, E);
    k_goff<<<1, GMAX>>>();

    int EB = (N + 7) / 8;
    int NB = (N + 255) / 256;

    // layer 0 (folded through embedding; fused gather + combine + degw)
    k_layer0<<<NB, 256>>>(x, gamma, beta, N);
    k_bn_final<<<1, 512>>>(0, gamma, beta, N, NB);

    // layer 1
    k_edge_agg<<<EB, 256>>>(1, 0, N);
    k_node<<<NB, 256>>>(1, 0, W1 + 4096, b1 + 64, W2 + 4096, W3 + 4096, b3 + 64, 2, N);
    k_bn_final<<<1, 512>>>(1, gamma, beta, N, NB);

    // layer 2
    k_edge_agg<<<EB, 256>>>(2, 1, N);
    k_node<<<NB, 256>>>(2, 1, W1 + 8192, b1 + 128, W2 + 8192, W3 + 8192, b3 + 128, 1, N);
    k_bn_final<<<1, 512>>>(2, gamma, beta, N, NB);

    // pooling (BN2+relu fused) + head
    k_poolhead<<<GMAX, 512>>>(1, 2, Wl1, bl1, Wl2, bl2, (float*)d_out, N);
}